// round 15
// baseline (speedup 1.0000x reference)
#include <cuda_runtime.h>
#include <cstdint>

#define N_CLASSES 2
#define N_FEATURES 100
#define DIM 10

#define BLOCK      256
#define TILE_ROWS  256
#define F4         25                          // float4 chunks per row
#define TILE_FLOATS (TILE_ROWS * N_FEATURES)   // 25600
#define TILE_BYTES  (TILE_FLOATS * 4)          // 102400
#define GRID       152                         // 1 block/SM on GB300
#define N_M        (N_CLASSES * N_FEATURES)    // 200

// Precomputed bilinear form Re(M)[k,a] (2 x 100) + completion counter.
__device__ float g_Mr[N_M];
__device__ int   g_done;

// ---------------------------------------------------------------------------
__device__ __forceinline__ void mbar_init(unsigned int mbar, unsigned int count) {
    asm volatile("mbarrier.init.shared.b64 [%0], %1;" :: "r"(mbar), "r"(count) : "memory");
}
__device__ __forceinline__ void mbar_expect_tx(unsigned int mbar, unsigned int bytes) {
    asm volatile("mbarrier.arrive.expect_tx.shared.b64 _, [%0], %1;"
                 :: "r"(mbar), "r"(bytes) : "memory");
}
__device__ __forceinline__ void mbar_wait_parity(unsigned int mbar, unsigned int parity) {
    asm volatile(
        "{\n\t"
        ".reg .pred P1;\n\t"
        "WAIT_LOOP_%=:\n\t"
        "mbarrier.try_wait.parity.acquire.cta.shared::cta.b64 P1, [%0], %1, 0x989680;\n\t"
        "@P1 bra.uni WAIT_DONE_%=;\n\t"
        "bra.uni WAIT_LOOP_%=;\n\t"
        "WAIT_DONE_%=:\n\t"
        "}"
        :: "r"(mbar), "r"(parity) : "memory");
}
__device__ __forceinline__ void bulk_copy_g2s(unsigned int dst_smem,
                                              const void* gsrc,
                                              unsigned int bytes,
                                              unsigned int mbar) {
    asm volatile(
        "cp.async.bulk.shared::cluster.global.mbarrier::complete_tx::bytes "
        "[%0], [%1], %2, [%3];"
        :: "r"(dst_smem), "l"(gsrc), "r"(bytes), "r"(mbar) : "memory");
}
__device__ __forceinline__ void fence_proxy_async_cta() {
    asm volatile("fence.proxy.async.shared::cta;" ::: "memory");
}

// ---------------------------------------------------------------------------
// Single fused kernel.
// Prologue: issue first tile copy; warps 0..199 (blocks 0..24) each compute one
// M element (overlapped with the copy); everyone spins on g_done, stages M to
// smem, then runs the persistent double-buffered bulk-copy GEMV pipeline.
__global__ __launch_bounds__(BLOCK) void gemv_kernel(const float* __restrict__ x,
                                                     float2* __restrict__ out,
                                                     int ntiles,
                                                     const float* __restrict__ A_re,
                                                     const float* __restrict__ A_im,
                                                     const float* __restrict__ psi_re,
                                                     const float* __restrict__ psi_im) {
    extern __shared__ float smem[];
    // Layout: [0,16) two mbarriers, [16,816) M, [816,...) two tile buffers.
    unsigned int smem_base = (unsigned int)__cvta_generic_to_shared(smem);
    unsigned int mbar[2] = { smem_base, smem_base + 8 };
    float* msh = smem + 4;                     // 2*N_FEATURES floats
    float* buf[2] = { smem + 204, smem + 204 + TILE_FLOATS };
    unsigned int buf_u32[2] = {
        (unsigned int)__cvta_generic_to_shared(buf[0]),
        (unsigned int)__cvta_generic_to_shared(buf[1]) };

    const int tid  = threadIdx.x;
    const int lane = tid & 31;
    const int wid  = tid >> 5;

    // Thread 0: init mbarriers and kick off the first tile copy immediately.
    const int first_tile = blockIdx.x;
    if (tid == 0) {
        mbar_init(mbar[0], 1);
        mbar_init(mbar[1], 1);
        fence_proxy_async_cta();
        if (first_tile < ntiles) {
            mbar_expect_tx(mbar[0], TILE_BYTES);
            bulk_copy_g2s(buf_u32[0], x + (size_t)first_tile * TILE_FLOATS,
                          TILE_BYTES, mbar[0]);
        }
    }

    // --- Fused M computation: global warp gw computes element gw (< 200). ---
    {
        int gw = blockIdx.x * (BLOCK / 32) + wid;
        if (gw < N_M) {
            int k = gw / N_FEATURES;
            int a = gw % N_FEATURES;
            float s = 0.0f;
            #pragma unroll
            for (int q = 0; q < 4; q++) {
                int m = lane + 32 * q;
                if (m < DIM * DIM) {
                    int i = m / DIM, j = m % DIM;
                    float pri = psi_re[i], pii = psi_im[i];
                    float prj = psi_re[j], pij = psi_im[j];
                    float wr = pri * prj + pii * pij;
                    float wi = pri * pij - pii * prj;
                    size_t off = ((size_t)k * DIM * DIM + m) * N_FEATURES + a;
                    s += A_re[off] * wr - A_im[off] * wi;
                }
            }
            #pragma unroll
            for (int o = 16; o > 0; o >>= 1) s += __shfl_xor_sync(0xFFFFFFFF, s, o);
            if (lane == 0) {
                g_Mr[gw] = s;
                __threadfence();
                atomicAdd(&g_done, 1);
            }
        }
    }

    // Spin until all 200 elements are published (first copy streams meanwhile).
    if (tid == 0) {
        while (*((volatile int*)&g_done) < N_M) __nanosleep(64);
        __threadfence();
    }
    __syncthreads();

    // Stage M into smem (50 float4 chunks).
    if (tid < (2 * N_FEATURES) / 4) {
        reinterpret_cast<float4*>(msh)[tid] =
            reinterpret_cast<const float4*>(g_Mr)[tid];
    }
    __syncthreads();

    // --- Persistent double-buffered pipeline. ---
    const int stride = gridDim.x;
    unsigned int phase[2] = { 0, 0 };
    int b = 0;
    for (int tile = first_tile; tile < ntiles; tile += stride, b ^= 1) {
        int next = tile + stride;
        if (next < ntiles && tid == 0) {
            // buf[b^1] was fully consumed (trailing __syncthreads last iter).
            fence_proxy_async_cta();
            mbar_expect_tx(mbar[b ^ 1], TILE_BYTES);
            bulk_copy_g2s(buf_u32[b ^ 1], x + (size_t)next * TILE_FLOATS,
                          TILE_BYTES, mbar[b ^ 1]);
        }

        mbar_wait_parity(mbar[b], phase[b]);
        phase[b] ^= 1;

        // Compute: thread t -> row t (row stride 25 float4s, odd => conflict-free).
        {
            const float4* xr = reinterpret_cast<const float4*>(buf[b]) + tid * F4;
            const float4* m0 = reinterpret_cast<const float4*>(msh);
            const float4* m1 = reinterpret_cast<const float4*>(msh + N_FEATURES);
            float a0 = 0.0f, a1 = 0.0f, c0 = 0.0f, c1 = 0.0f;
            #pragma unroll
            for (int i = 0; i < F4; i += 2) {
                float4 xv = xr[i];
                float4 u = m0[i];
                float4 v = m1[i];
                a0 += xv.x * u.x + xv.y * u.y + xv.z * u.z + xv.w * u.w;
                c0 += xv.x * v.x + xv.y * v.y + xv.z * v.z + xv.w * v.w;
                if (i + 1 < F4) {
                    float4 xw = xr[i + 1];
                    float4 u1 = m0[i + 1];
                    float4 v1 = m1[i + 1];
                    a1 += xw.x * u1.x + xw.y * u1.y + xw.z * u1.z + xw.w * u1.w;
                    c1 += xw.x * v1.x + xw.y * v1.y + xw.z * v1.z + xw.w * v1.w;
                }
            }
            out[tile * TILE_ROWS + tid] = make_float2(a0 + a1, c0 + c1);
        }
        __syncthreads();   // all reads of buf[b] done before it is refilled
    }
}

// ---------------------------------------------------------------------------
extern "C" void kernel_launch(void* const* d_in, const int* in_sizes, int n_in,
                              void* d_out, int out_size) {
    const float* x      = (const float*)d_in[0];
    const float* A_re   = (const float*)d_in[1];
    const float* A_im   = (const float*)d_in[2];
    const float* psi_re = (const float*)d_in[3];
    const float* psi_im = (const float*)d_in[4];
    float2* out = (float2*)d_out;

    int T = in_sizes[0] / N_FEATURES;   // 262144
    int ntiles = T / TILE_ROWS;         // 1024

    // Reset the M-publication counter (captured as a memset node).
    void* done_addr = nullptr;
    cudaGetSymbolAddress(&done_addr, g_done);
    cudaMemsetAsync(done_addr, 0, sizeof(int));

    // 16 B mbarriers + 800 B M + 2 x 102400 B buffers = 205616 B
    const int smem_bytes = 16 + 2 * N_FEATURES * 4 + 2 * TILE_BYTES;
    cudaFuncSetAttribute(gemv_kernel,
                         cudaFuncAttributeMaxDynamicSharedMemorySize, smem_bytes);

    gemv_kernel<<<GRID, BLOCK, smem_bytes>>>(x, out, ntiles,
                                             A_re, A_im, psi_re, psi_im);
}